// round 4
// baseline (speedup 1.0000x reference)
#include <cuda_runtime.h>
#include <cuda_bf16.h>
#include <cstddef>

// ---------------------------------------------------------------------------
// RoutedAllFC round 2: fp32 FFMA2 conv stack with multi-pixel-per-thread
// (PX) to raise FMA:LDS ratio; conv4 CI-split into 4 partial pre-pool slices
// (no atomics) with finalize fused into the BN kernel.
// ---------------------------------------------------------------------------

#define B_   64
#define CH_  160
#define EPS_ 1e-5f

__device__ float g_y1[B_ * CH_ * 32 * 32];
__device__ float g_y2[B_ * CH_ * 16 * 16];
__device__ float g_y3[B_ * CH_ * 8 * 8];
__device__ float g_pre4[4][B_ * CH_ * 8 * 8];   // conv4 partial pre-pool slices
__device__ float g_feat[B_ * 2560];
__device__ float g_h1[B_ * 320];
__device__ float g_h2[B_ * 320];

// ---- packed f32x2 helpers --------------------------------------------------
__device__ __forceinline__ unsigned long long pk2(float x) {
    unsigned long long r;
    asm("mov.b64 %0, {%1, %1};" : "=l"(r) : "f"(x));
    return r;
}
__device__ __forceinline__ void ffma2(unsigned long long& d,
                                      unsigned long long a,
                                      unsigned long long b) {
    asm("fma.rn.f32x2 %0, %1, %2, %3;" : "=l"(d) : "l"(a), "l"(b), "l"(d));
}
__device__ __forceinline__ float2 unpk(unsigned long long v) {
    float2 f;
    asm("mov.b64 {%0, %1}, %2;" : "=f"(f.x), "=f"(f.y) : "l"(v));
    return f;
}

// ---------------------------------------------------------------------------
// Fused conv3x3(pad1)+bias+ReLU+maxpool2. Thread owns PX adjacent pooled
// pixels (x-direction) for CO_T output channels (as f32x2 channel pairs), so
// each weight LDS.64 feeds 4*PX FFMA2s.
// ---------------------------------------------------------------------------
template <int CI, int HIN, int WIN, int THP, int TWPT, int PX, int CG,
          int CO_T, int CICH>
__global__ void __launch_bounds__(THP * TWPT * CG)
conv_pool(const float* __restrict__ in, const float* __restrict__ Wt,
          const float* __restrict__ bias, float* __restrict__ out) {
    constexpr int CO = 160;
    constexpr int HP = HIN / 2, WP = WIN / 2;
    constexpr int TWP = TWPT * PX;          // pooled tile width
    constexpr int TH = 2 * THP, TW = 2 * TWP;
    constexpr int SH = TH + 2, SWD = TW + 2;
    constexpr int T = THP * TWPT * CG;
    constexpr int CO_BLK = CG * CO_T;
    constexpr int NP = CO_T / 2;
    static_assert(CO_T % 2 == 0, "channel pairing requires even CO_T");

    __shared__ float s_in[CICH][SH][SWD];
    __shared__ float s_w[CICH][9][CO_BLK];

    const int tid = threadIdx.x;
    const int cg   = tid / (THP * TWPT);
    const int pix  = tid % (THP * TWPT);
    const int lpy  = pix / TWPT, lpxt = pix % TWPT;
    const int nimg = blockIdx.z;
    const int cob0 = blockIdx.y * CO_BLK;
    constexpr int TILESX = WP / TWP;
    const int tpy0 = (blockIdx.x / TILESX) * THP;
    const int tpx0 = (blockIdx.x % TILESX) * TWP;
    const int iy0 = 2 * tpy0 - 1, ix0 = 2 * tpx0 - 1;

    unsigned long long acc[NP][PX][4];
#pragma unroll
    for (int p = 0; p < NP; p++)
#pragma unroll
        for (int px = 0; px < PX; px++)
#pragma unroll
            for (int q = 0; q < 4; q++) acc[p][px][4 - 4 + q] = 0ull;

    for (int cc = 0; cc < CI; cc += CICH) {
        __syncthreads();
        for (int idx = tid; idx < CICH * SH * SWD; idx += T) {
            int cl  = idx / (SH * SWD);
            int rem = idx - cl * (SH * SWD);
            int iy  = rem / SWD, ix = rem - iy * SWD;
            int gy = iy0 + iy, gx = ix0 + ix;
            float v = 0.f;
            if ((unsigned)gy < (unsigned)HIN && (unsigned)gx < (unsigned)WIN)
                v = in[(((size_t)nimg * CI + (cc + cl)) * HIN + gy) * WIN + gx];
            (&s_in[0][0][0])[idx] = v;
        }
        for (int idx = tid; idx < CICH * 9 * CO_BLK; idx += T) {
            int cl  = idx / (9 * CO_BLK);
            int rem = idx - cl * (9 * CO_BLK);
            int k   = rem / CO_BLK;
            int col = rem - k * CO_BLK;
            (&s_w[0][0][0])[idx] =
                Wt[((size_t)(cob0 + col) * CI + (cc + cl)) * 9 + k];
        }
        __syncthreads();

#pragma unroll
        for (int cl = 0; cl < CICH; cl++) {
            const float* sp = &s_in[cl][2 * lpy][2 * lpxt * PX];
            float ip[4][2 * PX + 2];
#pragma unroll
            for (int r = 0; r < 4; r++)
#pragma unroll
                for (int c = 0; c <= PX; c++) {
                    float2 a = *(const float2*)(sp + r * SWD + 2 * c);
                    ip[r][2 * c] = a.x;
                    ip[r][2 * c + 1] = a.y;
                }
#pragma unroll
            for (int ky = 0; ky < 3; ky++)
#pragma unroll
                for (int kx = 0; kx < 3; kx++) {
                    const float* wp = &s_w[cl][ky * 3 + kx][cg * CO_T];
                    unsigned long long w2[NP];
#pragma unroll
                    for (int p = 0; p < NP; p++)
                        w2[p] = *(const unsigned long long*)(wp + 2 * p);
#pragma unroll
                    for (int px = 0; px < PX; px++) {
                        unsigned long long i00 = pk2(ip[ky][kx + 2 * px]);
                        unsigned long long i01 = pk2(ip[ky][kx + 2 * px + 1]);
                        unsigned long long i10 = pk2(ip[ky + 1][kx + 2 * px]);
                        unsigned long long i11 = pk2(ip[ky + 1][kx + 2 * px + 1]);
#pragma unroll
                        for (int p = 0; p < NP; p++) {
                            ffma2(acc[p][px][0], w2[p], i00);
                            ffma2(acc[p][px][1], w2[p], i01);
                            ffma2(acc[p][px][2], w2[p], i10);
                            ffma2(acc[p][px][3], w2[p], i11);
                        }
                    }
                }
        }
    }

#pragma unroll
    for (int p = 0; p < NP; p++) {
        int co = cob0 + cg * CO_T + 2 * p;
        float blo = bias[co], bhi = bias[co + 1];
#pragma unroll
        for (int px = 0; px < PX; px++) {
            float2 m0 = unpk(acc[p][px][0]), m1 = unpk(acc[p][px][1]);
            float2 m2 = unpk(acc[p][px][2]), m3 = unpk(acc[p][px][3]);
            float lo = fmaxf(fmaxf(m0.x, m1.x), fmaxf(m2.x, m3.x)) + blo;
            float hi = fmaxf(fmaxf(m0.y, m1.y), fmaxf(m2.y, m3.y)) + bhi;
            lo = fmaxf(lo, 0.f);
            hi = fmaxf(hi, 0.f);
            size_t ob = (((size_t)nimg * CO + co) * HP + (tpy0 + lpy)) * WP +
                        (tpx0 + lpxt * PX + px);
            out[ob] = lo;
            out[ob + (size_t)HP * WP] = hi;
        }
    }
}

// ---------------------------------------------------------------------------
// conv4 partial: CI split across blockIdx.x into 4 slices of 40 channels.
// Stores raw pre-pool conv partial sums (no bias/relu/pool) to its own slice.
// 128 thr = 8 pixthreads (4 pooled rows x 2 x-pairs, PX=2) x 16 cg (CO_T=2).
// ---------------------------------------------------------------------------
__global__ void __launch_bounds__(128)
conv4_part(const float* __restrict__ in, const float* __restrict__ Wt,
           float* __restrict__ pre) {
    constexpr int CI = 160, CIS = 40, CICH = 8, CO = 160, CO_BLK = 32;
    __shared__ float s_in[CICH][10][10];
    __shared__ float s_w[CICH][9][CO_BLK];

    const int tid = threadIdx.x;
    const int cg = tid / 8;            // 16 channel groups, 2 ch each
    const int pixt = tid % 8;
    const int lpy = pixt / 2, lpxt = pixt % 2;   // pooled row, x-pair id
    const int ci0 = blockIdx.x * CIS;
    const int cob0 = blockIdx.y * CO_BLK;
    const int nimg = blockIdx.z;
    float* slice = pre + (size_t)blockIdx.x * (B_ * CH_ * 64);

    unsigned long long acc[2][4];      // [px][tap]
#pragma unroll
    for (int px = 0; px < 2; px++)
#pragma unroll
        for (int q = 0; q < 4; q++) acc[px][q] = 0ull;

    for (int cc = 0; cc < CIS; cc += CICH) {
        __syncthreads();
        for (int idx = tid; idx < CICH * 100; idx += 128) {
            int cl = idx / 100, rem = idx - cl * 100;
            int iy = rem / 10, ix = rem - iy * 10;
            int gy = iy - 1, gx = ix - 1;
            float v = 0.f;
            if ((unsigned)gy < 8u && (unsigned)gx < 8u)
                v = in[(((size_t)nimg * CI + (ci0 + cc + cl)) * 8 + gy) * 8 + gx];
            (&s_in[0][0][0])[idx] = v;
        }
        for (int idx = tid; idx < CICH * 9 * CO_BLK; idx += 128) {
            int cl = idx / (9 * CO_BLK);
            int rem = idx - cl * (9 * CO_BLK);
            int k = rem / CO_BLK, col = rem - k * CO_BLK;
            (&s_w[0][0][0])[idx] =
                Wt[((size_t)(cob0 + col) * CI + (ci0 + cc + cl)) * 9 + k];
        }
        __syncthreads();

#pragma unroll
        for (int cl = 0; cl < CICH; cl++) {
            const float* sp = &s_in[cl][2 * lpy][4 * lpxt];
            float ip[4][6];
#pragma unroll
            for (int r = 0; r < 4; r++)
#pragma unroll
                for (int c = 0; c < 3; c++) {
                    float2 a = *(const float2*)(sp + r * 10 + 2 * c);
                    ip[r][2 * c] = a.x;
                    ip[r][2 * c + 1] = a.y;
                }
#pragma unroll
            for (int ky = 0; ky < 3; ky++)
#pragma unroll
                for (int kx = 0; kx < 3; kx++) {
                    unsigned long long w2 = *(const unsigned long long*)
                        (&s_w[cl][ky * 3 + kx][cg * 2]);
#pragma unroll
                    for (int px = 0; px < 2; px++) {
                        unsigned long long i00 = pk2(ip[ky][kx + 2 * px]);
                        unsigned long long i01 = pk2(ip[ky][kx + 2 * px + 1]);
                        unsigned long long i10 = pk2(ip[ky + 1][kx + 2 * px]);
                        unsigned long long i11 = pk2(ip[ky + 1][kx + 2 * px + 1]);
                        ffma2(acc[px][0], w2, i00);
                        ffma2(acc[px][1], w2, i01);
                        ffma2(acc[px][2], w2, i10);
                        ffma2(acc[px][3], w2, i11);
                    }
                }
        }
    }

    // store pre-pool partials: taps (dy,dx) at (2*py+dy, 2*pxp+dx), ch pair.
    int co = cob0 + cg * 2;
#pragma unroll
    for (int px = 0; px < 2; px++) {
        int pxp = lpxt * 2 + px;   // pooled x 0..3
#pragma unroll
        for (int dy = 0; dy < 2; dy++)
#pragma unroll
            for (int dx = 0; dx < 2; dx++) {
                float2 v = unpk(acc[px][dy * 2 + dx]);
                size_t a = (((size_t)nimg * CO + co) * 8 + (2 * lpy + dy)) * 8 +
                           (2 * pxp + dx);
                slice[a] = v.x;
                slice[a + 64] = v.y;   // next channel plane (8*8)
            }
    }
}

// ---------------------------------------------------------------------------
// Fused conv4 finalize (sum 4 CI-slices, +bias, ReLU, maxpool2) + BatchNorm
// (batch stats) + affine + flatten. One block per channel, 1024 values.
// ---------------------------------------------------------------------------
__global__ void __launch_bounds__(256)
bn_finalize(const float* __restrict__ pre, const float* __restrict__ b4,
            const float* __restrict__ gamma, const float* __restrict__ beta,
            float* __restrict__ feat) {
    constexpr size_t SL = (size_t)B_ * CH_ * 64;
    int c = blockIdx.x, tid = threadIdx.x;
    float bc = b4[c];
    int g0 = tid * 4;
    int n = g0 >> 4;
    float v[4];
#pragma unroll
    for (int j = 0; j < 4; j++) {
        int g = g0 + j;
        int pp = g & 15;
        int py = pp >> 2, px = pp & 3;
        size_t base = (((size_t)n * CH_ + c) * 8 + 2 * py) * 8 + 2 * px;
        float s00 = 0.f, s01 = 0.f, s10 = 0.f, s11 = 0.f;
#pragma unroll
        for (int s = 0; s < 4; s++) {
            float2 r0 = *(const float2*)(pre + s * SL + base);
            float2 r1 = *(const float2*)(pre + s * SL + base + 8);
            s00 += r0.x; s01 += r0.y; s10 += r1.x; s11 += r1.y;
        }
        float m = fmaxf(fmaxf(s00, s01), fmaxf(s10, s11)) + bc;
        v[j] = fmaxf(m, 0.f);
    }
    float s = v[0] + v[1] + v[2] + v[3];
    float q = v[0] * v[0] + v[1] * v[1] + v[2] * v[2] + v[3] * v[3];
#pragma unroll
    for (int off = 16; off; off >>= 1) {
        s += __shfl_xor_sync(0xffffffffu, s, off);
        q += __shfl_xor_sync(0xffffffffu, q, off);
    }
    __shared__ float rs[8], rq[8];
    __shared__ float s_scale, s_shift;
    int w = tid >> 5, lane = tid & 31;
    if (!lane) { rs[w] = s; rq[w] = q; }
    __syncthreads();
    if (tid == 0) {
        float S = 0.f, Q = 0.f;
#pragma unroll
        for (int j = 0; j < 8; j++) { S += rs[j]; Q += rq[j]; }
        float mean = S * (1.f / 1024.f);
        float var  = Q * (1.f / 1024.f) - mean * mean;
        float r = rsqrtf(var + EPS_);
        float gm = gamma[c] * r;
        s_scale = gm;
        s_shift = beta[c] - mean * gm;
    }
    __syncthreads();
    float gm = s_scale, bt = s_shift;
    float4 o = make_float4(v[0] * gm + bt, v[1] * gm + bt,
                           v[2] * gm + bt, v[3] * gm + bt);
    *(float4*)(feat + (size_t)n * 2560 + c * 16 + (g0 & 15)) = o;
}

// ---------------------------------------------------------------------------
// Routed linear: warp per output element.
// ---------------------------------------------------------------------------
template <bool RELU>
__global__ void __launch_bounds__(256)
fc_routed(const float* __restrict__ X, const float* __restrict__ Wb,
          const float* __restrict__ Bb, const int* __restrict__ act,
          float* __restrict__ Y, int IN, int OD) {
    int n = blockIdx.y;
    int w = threadIdx.x >> 5, lane = threadIdx.x & 31;
    int o = blockIdx.x * (blockDim.x >> 5) + w;
    if (o >= OD) return;
    int e = act[n];
    const float* wr = Wb + ((size_t)e * OD + o) * IN;
    const float* xr = X + (size_t)n * IN;
    float s = 0.f;
    for (int i = lane * 4; i < IN; i += 128) {
        float4 a = *(const float4*)(wr + i);
        float4 b = *(const float4*)(xr + i);
        s += a.x * b.x + a.y * b.y + a.z * b.z + a.w * b.w;
    }
#pragma unroll
    for (int off = 16; off; off >>= 1) s += __shfl_xor_sync(0xffffffffu, s, off);
    if (!lane) {
        float v = s + Bb[(size_t)e * OD + o];
        if (RELU) v = fmaxf(v, 0.f);
        Y[(size_t)n * OD + o] = v;
    }
}

// ---------------------------------------------------------------------------
extern "C" void kernel_launch(void* const* d_in, const int* in_sizes, int n_in,
                              void* d_out, int out_size) {
    const float* x   = (const float*)d_in[0];
    const int* a1    = (const int*)d_in[1];
    const int* a2    = (const int*)d_in[2];
    const int* a3    = (const int*)d_in[3];
    const float* W1  = (const float*)d_in[4];
    const float* b1  = (const float*)d_in[5];
    const float* W2  = (const float*)d_in[6];
    const float* b2  = (const float*)d_in[7];
    const float* W3  = (const float*)d_in[8];
    const float* b3  = (const float*)d_in[9];
    const float* W4  = (const float*)d_in[10];
    const float* b4  = (const float*)d_in[11];
    const float* gam = (const float*)d_in[12];
    const float* bet = (const float*)d_in[13];
    const float* E1W = (const float*)d_in[14];
    const float* E1b = (const float*)d_in[15];
    const float* E2W = (const float*)d_in[16];
    const float* E2b = (const float*)d_in[17];
    const float* E3W = (const float*)d_in[18];
    const float* E3b = (const float*)d_in[19];
    float* out = (float*)d_out;

    float *y1, *y2, *y3, *pre4, *feat, *h1, *h2;
    cudaGetSymbolAddress((void**)&y1, g_y1);
    cudaGetSymbolAddress((void**)&y2, g_y2);
    cudaGetSymbolAddress((void**)&y3, g_y3);
    cudaGetSymbolAddress((void**)&pre4, g_pre4);
    cudaGetSymbolAddress((void**)&feat, g_feat);
    cudaGetSymbolAddress((void**)&h1, g_h1);
    cudaGetSymbolAddress((void**)&h2, g_h2);

    // conv1: 3->160, 64x64 -> pooled 32x32; PX=1, CO_BLK=8.
    conv_pool<3, 64, 64, 16, 16, 1, 1, 8, 3>
        <<<dim3(4, 20, 64), 256>>>(x, W1, b1, y1);
    // conv2: 160->160, 32x32 -> 16x16; PX=2, CG=2, CO_T=8 -> CO_BLK=16.
    conv_pool<160, 32, 32, 16, 8, 2, 2, 8, 8>
        <<<dim3(1, 10, 64), 256>>>(y1, W2, b2, y2);
    // conv3: 160->160, 16x16 -> 8x8; PX=2, CG=4, CO_T=4 -> CO_BLK=16.
    conv_pool<160, 16, 16, 8, 4, 2, 4, 4, 8>
        <<<dim3(1, 10, 64), 128>>>(y2, W3, b3, y3);
    // conv4 partials: CI split x4, CO_BLK=32.
    conv4_part<<<dim3(4, 5, 64), 128>>>(y3, W4, pre4);
    // finalize conv4 + BN + flatten.
    bn_finalize<<<160, 256>>>(pre4, b4, gam, bet, feat);

    fc_routed<true ><<<dim3(40, 64), 256>>>(feat, E1W, E1b, a1, h1, 2560, 320);
    fc_routed<true ><<<dim3(40, 64), 256>>>(h1,   E2W, E2b, a2, h2, 320, 320);
    fc_routed<false><<<dim3(2, 64),  256>>>(h2,   E3W, E3b, a3, out, 320, 10);
}

// round 5
// speedup vs baseline: 1.0037x; 1.0037x over previous
#include <cuda_runtime.h>
#include <cuda_bf16.h>
#include <cstddef>

// ---------------------------------------------------------------------------
// RoutedAllFC round 2: fp32 FFMA2 conv stack with multi-pixel-per-thread
// (PX) to raise FMA:LDS ratio; conv4 CI-split into 4 partial pre-pool slices
// (no atomics) with finalize fused into the BN kernel.
// ---------------------------------------------------------------------------

#define B_   64
#define CH_  160
#define EPS_ 1e-5f

__device__ float g_y1[B_ * CH_ * 32 * 32];
__device__ float g_y2[B_ * CH_ * 16 * 16];
__device__ float g_y3[B_ * CH_ * 8 * 8];
__device__ float g_pre4[4][B_ * CH_ * 8 * 8];   // conv4 partial pre-pool slices
__device__ float g_feat[B_ * 2560];
__device__ float g_h1[B_ * 320];
__device__ float g_h2[B_ * 320];

// ---- packed f32x2 helpers --------------------------------------------------
__device__ __forceinline__ unsigned long long pk2(float x) {
    unsigned long long r;
    asm("mov.b64 %0, {%1, %1};" : "=l"(r) : "f"(x));
    return r;
}
__device__ __forceinline__ void ffma2(unsigned long long& d,
                                      unsigned long long a,
                                      unsigned long long b) {
    asm("fma.rn.f32x2 %0, %1, %2, %3;" : "=l"(d) : "l"(a), "l"(b), "l"(d));
}
__device__ __forceinline__ float2 unpk(unsigned long long v) {
    float2 f;
    asm("mov.b64 {%0, %1}, %2;" : "=f"(f.x), "=f"(f.y) : "l"(v));
    return f;
}

// ---------------------------------------------------------------------------
// Fused conv3x3(pad1)+bias+ReLU+maxpool2. Thread owns PX adjacent pooled
// pixels (x-direction) for CO_T output channels (as f32x2 channel pairs), so
// each weight LDS.64 feeds 4*PX FFMA2s.
// ---------------------------------------------------------------------------
template <int CI, int HIN, int WIN, int THP, int TWPT, int PX, int CG,
          int CO_T, int CICH>
__global__ void __launch_bounds__(THP * TWPT * CG)
conv_pool(const float* __restrict__ in, const float* __restrict__ Wt,
          const float* __restrict__ bias, float* __restrict__ out) {
    constexpr int CO = 160;
    constexpr int HP = HIN / 2, WP = WIN / 2;
    constexpr int TWP = TWPT * PX;          // pooled tile width
    constexpr int TH = 2 * THP, TW = 2 * TWP;
    constexpr int SH = TH + 2, SWD = TW + 2;
    constexpr int T = THP * TWPT * CG;
    constexpr int CO_BLK = CG * CO_T;
    constexpr int NP = CO_T / 2;
    static_assert(CO_T % 2 == 0, "channel pairing requires even CO_T");

    __shared__ float s_in[CICH][SH][SWD];
    __shared__ float s_w[CICH][9][CO_BLK];

    const int tid = threadIdx.x;
    const int cg   = tid / (THP * TWPT);
    const int pix  = tid % (THP * TWPT);
    const int lpy  = pix / TWPT, lpxt = pix % TWPT;
    const int nimg = blockIdx.z;
    const int cob0 = blockIdx.y * CO_BLK;
    constexpr int TILESX = WP / TWP;
    const int tpy0 = (blockIdx.x / TILESX) * THP;
    const int tpx0 = (blockIdx.x % TILESX) * TWP;
    const int iy0 = 2 * tpy0 - 1, ix0 = 2 * tpx0 - 1;

    unsigned long long acc[NP][PX][4];
#pragma unroll
    for (int p = 0; p < NP; p++)
#pragma unroll
        for (int px = 0; px < PX; px++)
#pragma unroll
            for (int q = 0; q < 4; q++) acc[p][px][4 - 4 + q] = 0ull;

    for (int cc = 0; cc < CI; cc += CICH) {
        __syncthreads();
        for (int idx = tid; idx < CICH * SH * SWD; idx += T) {
            int cl  = idx / (SH * SWD);
            int rem = idx - cl * (SH * SWD);
            int iy  = rem / SWD, ix = rem - iy * SWD;
            int gy = iy0 + iy, gx = ix0 + ix;
            float v = 0.f;
            if ((unsigned)gy < (unsigned)HIN && (unsigned)gx < (unsigned)WIN)
                v = in[(((size_t)nimg * CI + (cc + cl)) * HIN + gy) * WIN + gx];
            (&s_in[0][0][0])[idx] = v;
        }
        for (int idx = tid; idx < CICH * 9 * CO_BLK; idx += T) {
            int cl  = idx / (9 * CO_BLK);
            int rem = idx - cl * (9 * CO_BLK);
            int k   = rem / CO_BLK;
            int col = rem - k * CO_BLK;
            (&s_w[0][0][0])[idx] =
                Wt[((size_t)(cob0 + col) * CI + (cc + cl)) * 9 + k];
        }
        __syncthreads();

#pragma unroll
        for (int cl = 0; cl < CICH; cl++) {
            const float* sp = &s_in[cl][2 * lpy][2 * lpxt * PX];
            float ip[4][2 * PX + 2];
#pragma unroll
            for (int r = 0; r < 4; r++)
#pragma unroll
                for (int c = 0; c <= PX; c++) {
                    float2 a = *(const float2*)(sp + r * SWD + 2 * c);
                    ip[r][2 * c] = a.x;
                    ip[r][2 * c + 1] = a.y;
                }
#pragma unroll
            for (int ky = 0; ky < 3; ky++)
#pragma unroll
                for (int kx = 0; kx < 3; kx++) {
                    const float* wp = &s_w[cl][ky * 3 + kx][cg * CO_T];
                    unsigned long long w2[NP];
#pragma unroll
                    for (int p = 0; p < NP; p++)
                        w2[p] = *(const unsigned long long*)(wp + 2 * p);
#pragma unroll
                    for (int px = 0; px < PX; px++) {
                        unsigned long long i00 = pk2(ip[ky][kx + 2 * px]);
                        unsigned long long i01 = pk2(ip[ky][kx + 2 * px + 1]);
                        unsigned long long i10 = pk2(ip[ky + 1][kx + 2 * px]);
                        unsigned long long i11 = pk2(ip[ky + 1][kx + 2 * px + 1]);
#pragma unroll
                        for (int p = 0; p < NP; p++) {
                            ffma2(acc[p][px][0], w2[p], i00);
                            ffma2(acc[p][px][1], w2[p], i01);
                            ffma2(acc[p][px][2], w2[p], i10);
                            ffma2(acc[p][px][3], w2[p], i11);
                        }
                    }
                }
        }
    }

#pragma unroll
    for (int p = 0; p < NP; p++) {
        int co = cob0 + cg * CO_T + 2 * p;
        float blo = bias[co], bhi = bias[co + 1];
#pragma unroll
        for (int px = 0; px < PX; px++) {
            float2 m0 = unpk(acc[p][px][0]), m1 = unpk(acc[p][px][1]);
            float2 m2 = unpk(acc[p][px][2]), m3 = unpk(acc[p][px][3]);
            float lo = fmaxf(fmaxf(m0.x, m1.x), fmaxf(m2.x, m3.x)) + blo;
            float hi = fmaxf(fmaxf(m0.y, m1.y), fmaxf(m2.y, m3.y)) + bhi;
            lo = fmaxf(lo, 0.f);
            hi = fmaxf(hi, 0.f);
            size_t ob = (((size_t)nimg * CO + co) * HP + (tpy0 + lpy)) * WP +
                        (tpx0 + lpxt * PX + px);
            out[ob] = lo;
            out[ob + (size_t)HP * WP] = hi;
        }
    }
}

// ---------------------------------------------------------------------------
// conv4 partial: CI split across blockIdx.x into 4 slices of 40 channels.
// Stores raw pre-pool conv partial sums (no bias/relu/pool) to its own slice.
// 128 thr = 8 pixthreads (4 pooled rows x 2 x-pairs, PX=2) x 16 cg (CO_T=2).
// ---------------------------------------------------------------------------
__global__ void __launch_bounds__(128)
conv4_part(const float* __restrict__ in, const float* __restrict__ Wt,
           float* __restrict__ pre) {
    constexpr int CI = 160, CIS = 40, CICH = 8, CO = 160, CO_BLK = 32;
    __shared__ float s_in[CICH][10][10];
    __shared__ float s_w[CICH][9][CO_BLK];

    const int tid = threadIdx.x;
    const int cg = tid / 8;            // 16 channel groups, 2 ch each
    const int pixt = tid % 8;
    const int lpy = pixt / 2, lpxt = pixt % 2;   // pooled row, x-pair id
    const int ci0 = blockIdx.x * CIS;
    const int cob0 = blockIdx.y * CO_BLK;
    const int nimg = blockIdx.z;
    float* slice = pre + (size_t)blockIdx.x * (B_ * CH_ * 64);

    unsigned long long acc[2][4];      // [px][tap]
#pragma unroll
    for (int px = 0; px < 2; px++)
#pragma unroll
        for (int q = 0; q < 4; q++) acc[px][q] = 0ull;

    for (int cc = 0; cc < CIS; cc += CICH) {
        __syncthreads();
        for (int idx = tid; idx < CICH * 100; idx += 128) {
            int cl = idx / 100, rem = idx - cl * 100;
            int iy = rem / 10, ix = rem - iy * 10;
            int gy = iy - 1, gx = ix - 1;
            float v = 0.f;
            if ((unsigned)gy < 8u && (unsigned)gx < 8u)
                v = in[(((size_t)nimg * CI + (ci0 + cc + cl)) * 8 + gy) * 8 + gx];
            (&s_in[0][0][0])[idx] = v;
        }
        for (int idx = tid; idx < CICH * 9 * CO_BLK; idx += 128) {
            int cl = idx / (9 * CO_BLK);
            int rem = idx - cl * (9 * CO_BLK);
            int k = rem / CO_BLK, col = rem - k * CO_BLK;
            (&s_w[0][0][0])[idx] =
                Wt[((size_t)(cob0 + col) * CI + (ci0 + cc + cl)) * 9 + k];
        }
        __syncthreads();

#pragma unroll
        for (int cl = 0; cl < CICH; cl++) {
            const float* sp = &s_in[cl][2 * lpy][4 * lpxt];
            float ip[4][6];
#pragma unroll
            for (int r = 0; r < 4; r++)
#pragma unroll
                for (int c = 0; c < 3; c++) {
                    float2 a = *(const float2*)(sp + r * 10 + 2 * c);
                    ip[r][2 * c] = a.x;
                    ip[r][2 * c + 1] = a.y;
                }
#pragma unroll
            for (int ky = 0; ky < 3; ky++)
#pragma unroll
                for (int kx = 0; kx < 3; kx++) {
                    unsigned long long w2 = *(const unsigned long long*)
                        (&s_w[cl][ky * 3 + kx][cg * 2]);
#pragma unroll
                    for (int px = 0; px < 2; px++) {
                        unsigned long long i00 = pk2(ip[ky][kx + 2 * px]);
                        unsigned long long i01 = pk2(ip[ky][kx + 2 * px + 1]);
                        unsigned long long i10 = pk2(ip[ky + 1][kx + 2 * px]);
                        unsigned long long i11 = pk2(ip[ky + 1][kx + 2 * px + 1]);
                        ffma2(acc[px][0], w2, i00);
                        ffma2(acc[px][1], w2, i01);
                        ffma2(acc[px][2], w2, i10);
                        ffma2(acc[px][3], w2, i11);
                    }
                }
        }
    }

    // store pre-pool partials: taps (dy,dx) at (2*py+dy, 2*pxp+dx), ch pair.
    int co = cob0 + cg * 2;
#pragma unroll
    for (int px = 0; px < 2; px++) {
        int pxp = lpxt * 2 + px;   // pooled x 0..3
#pragma unroll
        for (int dy = 0; dy < 2; dy++)
#pragma unroll
            for (int dx = 0; dx < 2; dx++) {
                float2 v = unpk(acc[px][dy * 2 + dx]);
                size_t a = (((size_t)nimg * CO + co) * 8 + (2 * lpy + dy)) * 8 +
                           (2 * pxp + dx);
                slice[a] = v.x;
                slice[a + 64] = v.y;   // next channel plane (8*8)
            }
    }
}

// ---------------------------------------------------------------------------
// Fused conv4 finalize (sum 4 CI-slices, +bias, ReLU, maxpool2) + BatchNorm
// (batch stats) + affine + flatten. One block per channel, 1024 values.
// ---------------------------------------------------------------------------
__global__ void __launch_bounds__(256)
bn_finalize(const float* __restrict__ pre, const float* __restrict__ b4,
            const float* __restrict__ gamma, const float* __restrict__ beta,
            float* __restrict__ feat) {
    constexpr size_t SL = (size_t)B_ * CH_ * 64;
    int c = blockIdx.x, tid = threadIdx.x;
    float bc = b4[c];
    int g0 = tid * 4;
    int n = g0 >> 4;
    float v[4];
#pragma unroll
    for (int j = 0; j < 4; j++) {
        int g = g0 + j;
        int pp = g & 15;
        int py = pp >> 2, px = pp & 3;
        size_t base = (((size_t)n * CH_ + c) * 8 + 2 * py) * 8 + 2 * px;
        float s00 = 0.f, s01 = 0.f, s10 = 0.f, s11 = 0.f;
#pragma unroll
        for (int s = 0; s < 4; s++) {
            float2 r0 = *(const float2*)(pre + s * SL + base);
            float2 r1 = *(const float2*)(pre + s * SL + base + 8);
            s00 += r0.x; s01 += r0.y; s10 += r1.x; s11 += r1.y;
        }
        float m = fmaxf(fmaxf(s00, s01), fmaxf(s10, s11)) + bc;
        v[j] = fmaxf(m, 0.f);
    }
    float s = v[0] + v[1] + v[2] + v[3];
    float q = v[0] * v[0] + v[1] * v[1] + v[2] * v[2] + v[3] * v[3];
#pragma unroll
    for (int off = 16; off; off >>= 1) {
        s += __shfl_xor_sync(0xffffffffu, s, off);
        q += __shfl_xor_sync(0xffffffffu, q, off);
    }
    __shared__ float rs[8], rq[8];
    __shared__ float s_scale, s_shift;
    int w = tid >> 5, lane = tid & 31;
    if (!lane) { rs[w] = s; rq[w] = q; }
    __syncthreads();
    if (tid == 0) {
        float S = 0.f, Q = 0.f;
#pragma unroll
        for (int j = 0; j < 8; j++) { S += rs[j]; Q += rq[j]; }
        float mean = S * (1.f / 1024.f);
        float var  = Q * (1.f / 1024.f) - mean * mean;
        float r = rsqrtf(var + EPS_);
        float gm = gamma[c] * r;
        s_scale = gm;
        s_shift = beta[c] - mean * gm;
    }
    __syncthreads();
    float gm = s_scale, bt = s_shift;
    float4 o = make_float4(v[0] * gm + bt, v[1] * gm + bt,
                           v[2] * gm + bt, v[3] * gm + bt);
    *(float4*)(feat + (size_t)n * 2560 + c * 16 + (g0 & 15)) = o;
}

// ---------------------------------------------------------------------------
// Routed linear: warp per output element.
// ---------------------------------------------------------------------------
template <bool RELU>
__global__ void __launch_bounds__(256)
fc_routed(const float* __restrict__ X, const float* __restrict__ Wb,
          const float* __restrict__ Bb, const int* __restrict__ act,
          float* __restrict__ Y, int IN, int OD) {
    int n = blockIdx.y;
    int w = threadIdx.x >> 5, lane = threadIdx.x & 31;
    int o = blockIdx.x * (blockDim.x >> 5) + w;
    if (o >= OD) return;
    int e = act[n];
    const float* wr = Wb + ((size_t)e * OD + o) * IN;
    const float* xr = X + (size_t)n * IN;
    float s = 0.f;
    for (int i = lane * 4; i < IN; i += 128) {
        float4 a = *(const float4*)(wr + i);
        float4 b = *(const float4*)(xr + i);
        s += a.x * b.x + a.y * b.y + a.z * b.z + a.w * b.w;
    }
#pragma unroll
    for (int off = 16; off; off >>= 1) s += __shfl_xor_sync(0xffffffffu, s, off);
    if (!lane) {
        float v = s + Bb[(size_t)e * OD + o];
        if (RELU) v = fmaxf(v, 0.f);
        Y[(size_t)n * OD + o] = v;
    }
}

// ---------------------------------------------------------------------------
extern "C" void kernel_launch(void* const* d_in, const int* in_sizes, int n_in,
                              void* d_out, int out_size) {
    const float* x   = (const float*)d_in[0];
    const int* a1    = (const int*)d_in[1];
    const int* a2    = (const int*)d_in[2];
    const int* a3    = (const int*)d_in[3];
    const float* W1  = (const float*)d_in[4];
    const float* b1  = (const float*)d_in[5];
    const float* W2  = (const float*)d_in[6];
    const float* b2  = (const float*)d_in[7];
    const float* W3  = (const float*)d_in[8];
    const float* b3  = (const float*)d_in[9];
    const float* W4  = (const float*)d_in[10];
    const float* b4  = (const float*)d_in[11];
    const float* gam = (const float*)d_in[12];
    const float* bet = (const float*)d_in[13];
    const float* E1W = (const float*)d_in[14];
    const float* E1b = (const float*)d_in[15];
    const float* E2W = (const float*)d_in[16];
    const float* E2b = (const float*)d_in[17];
    const float* E3W = (const float*)d_in[18];
    const float* E3b = (const float*)d_in[19];
    float* out = (float*)d_out;

    float *y1, *y2, *y3, *pre4, *feat, *h1, *h2;
    cudaGetSymbolAddress((void**)&y1, g_y1);
    cudaGetSymbolAddress((void**)&y2, g_y2);
    cudaGetSymbolAddress((void**)&y3, g_y3);
    cudaGetSymbolAddress((void**)&pre4, g_pre4);
    cudaGetSymbolAddress((void**)&feat, g_feat);
    cudaGetSymbolAddress((void**)&h1, g_h1);
    cudaGetSymbolAddress((void**)&h2, g_h2);

    // conv1: 3->160, 64x64 -> pooled 32x32; PX=1, CO_BLK=8.
    conv_pool<3, 64, 64, 16, 16, 1, 1, 8, 3>
        <<<dim3(4, 20, 64), 256>>>(x, W1, b1, y1);
    // conv2: 160->160, 32x32 -> 16x16; PX=2, CG=2, CO_T=8 -> CO_BLK=16.
    conv_pool<160, 32, 32, 16, 8, 2, 2, 8, 8>
        <<<dim3(1, 10, 64), 256>>>(y1, W2, b2, y2);
    // conv3: 160->160, 16x16 -> 8x8; PX=2, CG=4, CO_T=4 -> CO_BLK=16.
    conv_pool<160, 16, 16, 8, 4, 2, 4, 4, 8>
        <<<dim3(1, 10, 64), 128>>>(y2, W3, b3, y3);
    // conv4 partials: CI split x4, CO_BLK=32.
    conv4_part<<<dim3(4, 5, 64), 128>>>(y3, W4, pre4);
    // finalize conv4 + BN + flatten.
    bn_finalize<<<160, 256>>>(pre4, b4, gam, bet, feat);

    fc_routed<true ><<<dim3(40, 64), 256>>>(feat, E1W, E1b, a1, h1, 2560, 320);
    fc_routed<true ><<<dim3(40, 64), 256>>>(h1,   E2W, E2b, a2, h2, 320, 320);
    fc_routed<false><<<dim3(2, 64),  256>>>(h2,   E3W, E3b, a3, out, 320, 10);
}